// round 1
// baseline (speedup 1.0000x reference)
#include <cuda_runtime.h>
#include <cuda_bf16.h>

// Problem constants
#define BATCH 2
#define SEQ   8192
#define CDIM  1024
#define HDIM  64
#define NROWS (BATCH * SEQ)        // 16384
#define QKVW  (3 * HDIM)           // 192 (q | k | v packed per row)

// Scratch for fused qkv: [NROWS][192], 12 MB (device global, no allocation)
__device__ float g_qkv[(size_t)NROWS * QKVW];

// ---------------------------------------------------------------------------
// QKV projection GEMM: C[m, y*64+n] = sum_k x[m,k] * W_y[k,n]
// BM=128, BN=64, BK=16, 256 threads, 8x4 register tile per thread.
// grid = (NROWS/128, 3); blockIdx.y selects Wq / Wk / Wv.
// ---------------------------------------------------------------------------
#define BM 128
#define BN 64
#define BK 16

__global__ __launch_bounds__(256)
void qkv_gemm(const float* __restrict__ x,
              const float* __restrict__ Wq,
              const float* __restrict__ Wk,
              const float* __restrict__ Wv)
{
    const int K = CDIM;
    const float* W = (blockIdx.y == 0) ? Wq : ((blockIdx.y == 1) ? Wk : Wv);
    const int m0 = blockIdx.x * BM;

    __shared__ float As[BK][BM];   // As[k][m]
    __shared__ float Bs[BK][BN];   // Bs[k][n]

    const int tid = threadIdx.x;
    const int tx  = tid & 15;      // n-direction, 16 threads
    const int ty  = tid >> 4;      // m-direction, 16 threads

    float acc[8][4];
    #pragma unroll
    for (int i = 0; i < 8; i++)
        #pragma unroll
        for (int j = 0; j < 4; j++)
            acc[i][j] = 0.0f;

    for (int k0 = 0; k0 < K; k0 += BK) {
        // Load A tile: 128 rows x 16 cols = 512 float4 -> 2 per thread
        #pragma unroll
        for (int l = 0; l < 2; l++) {
            int idx = tid + l * 256;     // 0..511
            int row = idx >> 2;          // 0..127
            int kq  = idx & 3;           // which float4 within the 16-wide row
            float4 va = *reinterpret_cast<const float4*>(
                x + (size_t)(m0 + row) * K + k0 + kq * 4);
            As[kq * 4 + 0][row] = va.x;
            As[kq * 4 + 1][row] = va.y;
            As[kq * 4 + 2][row] = va.z;
            As[kq * 4 + 3][row] = va.w;
        }
        // Load B tile: 16 rows x 64 cols = 256 float4 -> 1 per thread
        {
            int row = tid >> 4;          // 0..15 (k)
            int c4  = tid & 15;          // 0..15 (float4 within 64-wide row)
            float4 vb = *reinterpret_cast<const float4*>(
                W + (size_t)(k0 + row) * HDIM + c4 * 4);
            Bs[row][c4 * 4 + 0] = vb.x;
            Bs[row][c4 * 4 + 1] = vb.y;
            Bs[row][c4 * 4 + 2] = vb.z;
            Bs[row][c4 * 4 + 3] = vb.w;
        }
        __syncthreads();

        #pragma unroll
        for (int kk = 0; kk < BK; kk++) {
            float4 a0 = *reinterpret_cast<const float4*>(&As[kk][ty * 8]);
            float4 a1 = *reinterpret_cast<const float4*>(&As[kk][ty * 8 + 4]);
            float4 bv = *reinterpret_cast<const float4*>(&Bs[kk][tx * 4]);
            float a[8] = {a0.x, a0.y, a0.z, a0.w, a1.x, a1.y, a1.z, a1.w};
            float b[4] = {bv.x, bv.y, bv.z, bv.w};
            #pragma unroll
            for (int i = 0; i < 8; i++)
                #pragma unroll
                for (int j = 0; j < 4; j++)
                    acc[i][j] = fmaf(a[i], b[j], acc[i][j]);
        }
        __syncthreads();
    }

    // Epilogue: write to g_qkv[m][blockIdx.y*64 + n], row stride 192
    float* outbase = g_qkv + (size_t)(m0 + ty * 8) * QKVW + blockIdx.y * HDIM + tx * 4;
    #pragma unroll
    for (int i = 0; i < 8; i++) {
        float4 v = make_float4(acc[i][0], acc[i][1], acc[i][2], acc[i][3]);
        *reinterpret_cast<float4*>(outbase + (size_t)i * QKVW) = v;
    }
}

// ---------------------------------------------------------------------------
// Windowed causal attention: one warp per query.
// scores_j = (q_i . k_j) / sqrt(64) for j in [i-16, i]; exact softmax; out = p.V
// ---------------------------------------------------------------------------
__global__ __launch_bounds__(256)
void attn_kernel(float* __restrict__ out)
{
    const int gw   = (blockIdx.x * 256 + threadIdx.x) >> 5;  // global warp = query row
    const int lane = threadIdx.x & 31;
    if (gw >= NROWS) return;

    const int b = gw >> 13;        // / 8192
    const int i = gw & (SEQ - 1);  // % 8192

    const float* qrow = g_qkv + (size_t)gw * QKVW;
    const float q0 = qrow[lane];
    const float q1 = qrow[lane + 32];

    float sc[17];
    float mx = -1e30f;
    #pragma unroll
    for (int t = 0; t < 17; t++) {
        int j = i - 16 + t;
        float d = -1e30f;
        if (j >= 0) {
            const float* kr = g_qkv + (size_t)(b * SEQ + j) * QKVW + HDIM;
            float p = q0 * kr[lane] + q1 * kr[lane + 32];
            #pragma unroll
            for (int o = 16; o > 0; o >>= 1)
                p += __shfl_xor_sync(0xffffffffu, p, o);
            d = p * 0.125f;   // 1/sqrt(64)
        }
        sc[t] = d;
        mx = fmaxf(mx, d);
    }

    float denom = 0.0f;
    #pragma unroll
    for (int t = 0; t < 17; t++) {
        sc[t] = __expf(sc[t] - mx);   // invalid slots: exp(-huge) -> 0
        denom += sc[t];
    }

    float o0 = 0.0f, o1 = 0.0f;
    #pragma unroll
    for (int t = 0; t < 17; t++) {
        int j = i - 16 + t;
        if (j >= 0) {
            const float* vr = g_qkv + (size_t)(b * SEQ + j) * QKVW + 2 * HDIM;
            o0 = fmaf(sc[t], vr[lane],      o0);
            o1 = fmaf(sc[t], vr[lane + 32], o1);
        }
    }
    const float inv = 1.0f / denom;
    out[(size_t)gw * HDIM + lane]      = o0 * inv;
    out[(size_t)gw * HDIM + lane + 32] = o1 * inv;
}

// ---------------------------------------------------------------------------
// Launch
// ---------------------------------------------------------------------------
extern "C" void kernel_launch(void* const* d_in, const int* in_sizes, int n_in,
                              void* d_out, int out_size)
{
    const float* x  = (const float*)d_in[0];
    const float* Wq = (const float*)d_in[1];
    const float* Wk = (const float*)d_in[2];
    const float* Wv = (const float*)d_in[3];
    float* out = (float*)d_out;

    dim3 grid_gemm(NROWS / BM, 3);
    qkv_gemm<<<grid_gemm, 256>>>(x, Wq, Wk, Wv);

    const int warps = NROWS;                     // one warp per query
    const int blocks = (warps * 32 + 255) / 256; // 2048
    attn_kernel<<<blocks, 256>>>(out);
}

// round 3
// speedup vs baseline: 2.5301x; 2.5301x over previous
#include <cuda_runtime.h>
#include <cuda_bf16.h>
#include <cstdint>

#define BATCH 2
#define SEQ   8192
#define CDIM  1024
#define HDIM  64
#define NROWS (BATCH * SEQ)   // 16384
#define QKVW  (3 * HDIM)      // 192

// ---- device scratch (no allocations) --------------------------------------
__device__ float         g_qkv[(size_t)NROWS * QKVW];     // 12 MB  q|k|v per row
__device__ __nv_bfloat16 g_wt_hi[QKVW * CDIM];            // W^T hi  [192][1024]
__device__ __nv_bfloat16 g_wt_lo[QKVW * CDIM];            // W^T lo

// ---- helpers ----------------------------------------------------------------
__device__ __forceinline__ uint32_t smem_u32(const void* p) {
    uint32_t a;
    asm("{ .reg .u64 t; cvta.to.shared.u64 t, %1; cvt.u32.u64 %0, t; }"
        : "=r"(a) : "l"(p));
    return a;
}
__device__ __forceinline__ void ldm_x4(uint32_t* r, uint32_t addr) {
    asm volatile("ldmatrix.sync.aligned.m8n8.x4.shared.b16 {%0,%1,%2,%3}, [%4];"
        : "=r"(r[0]), "=r"(r[1]), "=r"(r[2]), "=r"(r[3]) : "r"(addr));
}
__device__ __forceinline__ void mma_bf16(float* c, const uint32_t* a, const uint32_t* b) {
    asm volatile("mma.sync.aligned.m16n8k16.row.col.f32.bf16.bf16.f32 "
        "{%0,%1,%2,%3}, {%4,%5,%6,%7}, {%8,%9}, {%0,%1,%2,%3};"
        : "+f"(c[0]), "+f"(c[1]), "+f"(c[2]), "+f"(c[3])
        : "r"(a[0]), "r"(a[1]), "r"(a[2]), "r"(a[3]), "r"(b[0]), "r"(b[1]));
}
#define CP_ASYNC16(sm, gm) \
    asm volatile("cp.async.cg.shared.global [%0], [%1], 16;" :: "r"(sm), "l"(gm) : "memory")
#define CP_COMMIT() asm volatile("cp.async.commit_group;" ::: "memory")
#define CP_WAIT0()  asm volatile("cp.async.wait_group 0;" ::: "memory")

__device__ __forceinline__ uint32_t pack_bf2(float a, float b) {
    __nv_bfloat162 t = __floats2bfloat162_rn(a, b);
    return *reinterpret_cast<uint32_t*>(&t);
}

// ---------------------------------------------------------------------------
// Pre-pass: W fp32 [1024][64] x3  ->  W^T hi/lo bf16 [192][1024]
// ---------------------------------------------------------------------------
__global__ void conv_w(const float* __restrict__ Wq,
                       const float* __restrict__ Wk,
                       const float* __restrict__ Wv) {
    int k = blockIdx.x;        // 0..1023
    int n = threadIdx.x;       // 0..191
    const float* W = (n < 64) ? Wq : ((n < 128) ? Wk : Wv);
    float v = W[k * 64 + (n & 63)];
    __nv_bfloat16 h = __float2bfloat16(v);
    float r = v - __bfloat162float(h);
    g_wt_hi[(size_t)n * CDIM + k] = h;
    g_wt_lo[(size_t)n * CDIM + k] = __float2bfloat16(r);
}

// ---------------------------------------------------------------------------
// HMMA GEMM: g_qkv[m][0..191] = x[m][:] @ [Wq|Wk|Wv], bf16 2-term split.
// BM=128, N=192, BK=32, 8 warps (4m x 2n), warp tile 32x96.
// ---------------------------------------------------------------------------
#define BM   128
#define BK   32
#define NC   (CDIM / BK)      // 32 chunks
#define SA   40               // smem row stride in halfs (80 B, conflict-free)
#define OFF_AHI 0
#define OFF_ALO (BM * SA * 2)                       // 10240
#define OFF_BHI (2 * BM * SA * 2)                   // 20480
#define OFF_BLO (OFF_BHI + QKVW * SA * 2)           // 35840
#define STAGE   (OFF_BLO + QKVW * SA * 2)           // 51200
#define GEMM_SMEM (2 * STAGE)                       // 102400

__global__ __launch_bounds__(256, 1)
void qkv_gemm_mma(const float* __restrict__ x) {
    extern __shared__ char sm[];
    const uint32_t smb = smem_u32(sm);

    const int tid  = threadIdx.x;
    const int wid  = tid >> 5;
    const int lane = tid & 31;
    const int wm   = wid >> 1;       // 0..3
    const int wn   = wid & 1;        // 0..1
    const int m0   = blockIdx.x * BM;

    float acc[2][12][4];
    #pragma unroll
    for (int mt = 0; mt < 2; mt++)
        #pragma unroll
        for (int nt = 0; nt < 12; nt++)
            #pragma unroll
            for (int q = 0; q < 4; q++) acc[mt][nt][q] = 0.f;

    // ldmatrix lane addressing
    const int a_row  = (lane & 15);
    const int a_col  = (lane >> 4) * 8;
    const int b_rowo = ((lane >> 4) << 3) + (lane & 7);
    const int b_col  = ((lane >> 3) & 1) * 8;

    // global-load lane mapping
    const int xrow = tid >> 3, xq4 = tid & 7;          // + l*32 rows
    const int bn = tid >> 2, bu = tid & 3;             // + l*64 rows

    float4 xf[4];

    // ---- prologue: chunk 0 ----
    {
        #pragma unroll
        for (int l = 0; l < 4; l++)
            xf[l] = *reinterpret_cast<const float4*>(
                x + (size_t)(m0 + xrow + l * 32) * CDIM + xq4 * 4);
        #pragma unroll
        for (int l = 0; l < 3; l++) {
            int n = bn + l * 64;
            uint32_t so = (uint32_t)(n * SA + bu * 8) * 2;
            CP_ASYNC16(smb + OFF_BHI + so, g_wt_hi + (size_t)n * CDIM + bu * 8);
            CP_ASYNC16(smb + OFF_BLO + so, g_wt_lo + (size_t)n * CDIM + bu * 8);
        }
        CP_COMMIT();
        #pragma unroll
        for (int l = 0; l < 4; l++) {
            int row = xrow + l * 32;
            float hx = __bfloat162float(__float2bfloat16(xf[l].x));
            float hy = __bfloat162float(__float2bfloat16(xf[l].y));
            float hz = __bfloat162float(__float2bfloat16(xf[l].z));
            float hw = __bfloat162float(__float2bfloat16(xf[l].w));
            uint2 hp = make_uint2(pack_bf2(xf[l].x, xf[l].y), pack_bf2(xf[l].z, xf[l].w));
            uint2 lp = make_uint2(pack_bf2(xf[l].x - hx, xf[l].y - hy),
                                  pack_bf2(xf[l].z - hz, xf[l].w - hw));
            uint32_t so = (uint32_t)(row * SA + xq4 * 4) * 2;
            *reinterpret_cast<uint2*>(sm + OFF_AHI + so) = hp;
            *reinterpret_cast<uint2*>(sm + OFF_ALO + so) = lp;
        }
        CP_WAIT0();
        __syncthreads();
    }

    for (int c = 0; c < NC; c++) {
        const int s = c & 1;
        const uint32_t st = smb + s * STAGE;
        const bool more = (c + 1 < NC);

        // ---- prefetch chunk c+1 ----
        if (more) {
            const int k1 = (c + 1) * BK;
            #pragma unroll
            for (int l = 0; l < 4; l++)
                xf[l] = *reinterpret_cast<const float4*>(
                    x + (size_t)(m0 + xrow + l * 32) * CDIM + k1 + xq4 * 4);
            const uint32_t stn = smb + (s ^ 1) * STAGE;
            #pragma unroll
            for (int l = 0; l < 3; l++) {
                int n = bn + l * 64;
                uint32_t so = (uint32_t)(n * SA + bu * 8) * 2;
                CP_ASYNC16(stn + OFF_BHI + so, g_wt_hi + (size_t)n * CDIM + k1 + bu * 8);
                CP_ASYNC16(stn + OFF_BLO + so, g_wt_lo + (size_t)n * CDIM + k1 + bu * 8);
            }
            CP_COMMIT();
        }

        // ---- compute chunk c ----
        #pragma unroll
        for (int ks = 0; ks < 2; ks++) {
            const int k0 = ks * 16;
            uint32_t ahi[2][4], alo[2][4], bf[6][4];
            #pragma unroll
            for (int mt = 0; mt < 2; mt++) {
                uint32_t ao = (uint32_t)((wm * 32 + mt * 16 + a_row) * SA + k0 + a_col) * 2;
                ldm_x4(ahi[mt], st + OFF_AHI + ao);
                ldm_x4(alo[mt], st + OFF_ALO + ao);
            }
            #pragma unroll
            for (int g = 0; g < 6; g++) {
                uint32_t bo = (uint32_t)((wn * 96 + g * 16 + b_rowo) * SA + k0 + b_col) * 2;
                ldm_x4(bf[g], st + OFF_BHI + bo);
            }
            #pragma unroll
            for (int mt = 0; mt < 2; mt++)
                #pragma unroll
                for (int g = 0; g < 6; g++) {
                    mma_bf16(acc[mt][2 * g],     ahi[mt], &bf[g][0]);
                    mma_bf16(acc[mt][2 * g + 1], ahi[mt], &bf[g][2]);
                    mma_bf16(acc[mt][2 * g],     alo[mt], &bf[g][0]);
                    mma_bf16(acc[mt][2 * g + 1], alo[mt], &bf[g][2]);
                }
            #pragma unroll
            for (int g = 0; g < 6; g++) {
                uint32_t bo = (uint32_t)((wn * 96 + g * 16 + b_rowo) * SA + k0 + b_col) * 2;
                ldm_x4(bf[g], st + OFF_BLO + bo);
            }
            #pragma unroll
            for (int mt = 0; mt < 2; mt++)
                #pragma unroll
                for (int g = 0; g < 6; g++) {
                    mma_bf16(acc[mt][2 * g],     ahi[mt], &bf[g][0]);
                    mma_bf16(acc[mt][2 * g + 1], ahi[mt], &bf[g][2]);
                }
        }

        // ---- store prefetched x into next stage ----
        if (more) {
            char* stn = sm + (s ^ 1) * STAGE;
            #pragma unroll
            for (int l = 0; l < 4; l++) {
                int row = xrow + l * 32;
                float hx = __bfloat162float(__float2bfloat16(xf[l].x));
                float hy = __bfloat162float(__float2bfloat16(xf[l].y));
                float hz = __bfloat162float(__float2bfloat16(xf[l].z));
                float hw = __bfloat162float(__float2bfloat16(xf[l].w));
                uint2 hp = make_uint2(pack_bf2(xf[l].x, xf[l].y), pack_bf2(xf[l].z, xf[l].w));
                uint2 lp = make_uint2(pack_bf2(xf[l].x - hx, xf[l].y - hy),
                                      pack_bf2(xf[l].z - hz, xf[l].w - hw));
                uint32_t so = (uint32_t)(row * SA + xq4 * 4) * 2;
                *reinterpret_cast<uint2*>(stn + OFF_AHI + so) = hp;
                *reinterpret_cast<uint2*>(stn + OFF_ALO + so) = lp;
            }
            CP_WAIT0();
            __syncthreads();
        }
    }

    // ---- epilogue ----
    const int grp = lane >> 2, tig = lane & 3;
    #pragma unroll
    for (int mt = 0; mt < 2; mt++) {
        const int row = m0 + wm * 32 + mt * 16 + grp;
        #pragma unroll
        for (int nt = 0; nt < 12; nt++) {
            const int col = wn * 96 + nt * 8 + tig * 2;
            *reinterpret_cast<float2*>(g_qkv + (size_t)row * QKVW + col) =
                make_float2(acc[mt][nt][0], acc[mt][nt][1]);
            *reinterpret_cast<float2*>(g_qkv + (size_t)(row + 8) * QKVW + col) =
                make_float2(acc[mt][nt][2], acc[mt][nt][3]);
        }
    }
}

// ---------------------------------------------------------------------------
// Attention: 128 queries/block, 2 lanes per query (dim halves), k/v in smem.
// smem row stride 66 words, half offset 33 -> conflict-free scalar LDS.
// ---------------------------------------------------------------------------
#define AT_ROWS 144
#define AT_STRIDE 66
#define ATT_SMEM (2 * AT_ROWS * AT_STRIDE * 4)   // 76032

__global__ __launch_bounds__(256)
void attn2(float* __restrict__ out) {
    extern __shared__ float smf[];
    float* const ks = smf;
    float* const vs = smf + AT_ROWS * AT_STRIDE;

    const int tid = threadIdx.x;
    const int b  = blockIdx.x >> 6;
    const int i0 = (blockIdx.x & 63) * 128;

    #pragma unroll
    for (int l = 0; l < 9; l++) {
        int lin = l * 256 + tid;           // 0..2303
        int idx = lin >> 4, c4 = lin & 15;
        int j = i0 - 16 + idx;
        float4 kv = make_float4(0.f, 0.f, 0.f, 0.f);
        float4 vv = make_float4(0.f, 0.f, 0.f, 0.f);
        if (j >= 0) {
            const float* src = g_qkv + (size_t)(b * SEQ + j) * QKVW;
            kv = *reinterpret_cast<const float4*>(src + HDIM + c4 * 4);
            vv = *reinterpret_cast<const float4*>(src + 2 * HDIM + c4 * 4);
        }
        int d = c4 * 4;
        int w = idx * AT_STRIDE + (d < 32 ? d : 33 + (d - 32));
        ks[w + 0] = kv.x; ks[w + 1] = kv.y; ks[w + 2] = kv.z; ks[w + 3] = kv.w;
        vs[w + 0] = vv.x; vs[w + 1] = vv.y; vs[w + 2] = vv.z; vs[w + 3] = vv.w;
    }

    const int lane = tid & 31;
    const int wrp = tid >> 5;
    const int qi = wrp * 16 + (lane & 15);   // 0..127
    const int h = lane >> 4;
    const int d0 = h * 32;
    const int i = i0 + qi;
    const size_t grow = (size_t)(b * SEQ + i);

    float q[32];
    {
        const float* qp = g_qkv + grow * QKVW + d0;
        #pragma unroll
        for (int cc = 0; cc < 32; cc += 4) {
            float4 t = *reinterpret_cast<const float4*>(qp + cc);
            q[cc] = t.x; q[cc + 1] = t.y; q[cc + 2] = t.z; q[cc + 3] = t.w;
        }
    }
    __syncthreads();

    float sc[17];
    float mx = -1e30f;
    #pragma unroll
    for (int t = 0; t < 17; t++) {
        const float* kr = ks + (qi + t) * AT_STRIDE + h * 33;
        float p0 = 0.f, p1 = 0.f, p2 = 0.f, p3 = 0.f;
        #pragma unroll
        for (int cc = 0; cc < 32; cc += 4) {
            p0 = fmaf(q[cc + 0], kr[cc + 0], p0);
            p1 = fmaf(q[cc + 1], kr[cc + 1], p1);
            p2 = fmaf(q[cc + 2], kr[cc + 2], p2);
            p3 = fmaf(q[cc + 3], kr[cc + 3], p3);
        }
        float p = (p0 + p1) + (p2 + p3);
        p += __shfl_xor_sync(0xffffffffu, p, 16);
        float d = (i - 16 + t >= 0) ? p * 0.125f : -1e30f;
        sc[t] = d;
        mx = fmaxf(mx, d);
    }

    float den = 0.f;
    #pragma unroll
    for (int t = 0; t < 17; t++) { sc[t] = __expf(sc[t] - mx); den += sc[t]; }
    const float inv = 1.0f / den;

    float* op = out + grow * HDIM + d0;
    #pragma unroll
    for (int cb = 0; cb < 32; cb += 4) {
        float a0 = 0.f, a1 = 0.f, a2 = 0.f, a3 = 0.f;
        #pragma unroll
        for (int t = 0; t < 17; t++) {
            const float* vr = vs + (qi + t) * AT_STRIDE + h * 33 + cb;
            a0 = fmaf(sc[t], vr[0], a0);
            a1 = fmaf(sc[t], vr[1], a1);
            a2 = fmaf(sc[t], vr[2], a2);
            a3 = fmaf(sc[t], vr[3], a3);
        }
        *reinterpret_cast<float4*>(op + cb) =
            make_float4(a0 * inv, a1 * inv, a2 * inv, a3 * inv);
    }
}

// ---------------------------------------------------------------------------
extern "C" void kernel_launch(void* const* d_in, const int* in_sizes, int n_in,
                              void* d_out, int out_size)
{
    const float* x  = (const float*)d_in[0];
    const float* Wq = (const float*)d_in[1];
    const float* Wk = (const float*)d_in[2];
    const float* Wv = (const float*)d_in[3];
    float* out = (float*)d_out;

    cudaFuncSetAttribute(qkv_gemm_mma, cudaFuncAttributeMaxDynamicSharedMemorySize, GEMM_SMEM);
    cudaFuncSetAttribute(attn2,        cudaFuncAttributeMaxDynamicSharedMemorySize, ATT_SMEM);

    conv_w<<<CDIM, QKVW>>>(Wq, Wk, Wv);
    qkv_gemm_mma<<<NROWS / BM, 256, GEMM_SMEM>>>(x);
    attn2<<<128, 256, ATT_SMEM>>>(out);
}

// round 4
// speedup vs baseline: 2.5962x; 1.0262x over previous
#include <cuda_runtime.h>
#include <cuda_bf16.h>
#include <cstdint>

#define BATCH 2
#define SEQ   8192
#define CDIM  1024
#define HDIM  64
#define NROWS (BATCH * SEQ)   // 16384
#define QKVW  (3 * HDIM)      // 192

// ---- device scratch (no allocations) --------------------------------------
__device__ float         g_qkv[(size_t)NROWS * QKVW];     // 12 MB  q|k|v per row
__device__ __nv_bfloat16 g_wt_hi[QKVW * CDIM];            // W^T hi  [192][1024]
__device__ __nv_bfloat16 g_wt_lo[QKVW * CDIM];            // W^T lo

// ---- helpers ----------------------------------------------------------------
__device__ __forceinline__ uint32_t smem_u32(const void* p) {
    uint32_t a;
    asm("{ .reg .u64 t; cvta.to.shared.u64 t, %1; cvt.u32.u64 %0, t; }"
        : "=r"(a) : "l"(p));
    return a;
}
__device__ __forceinline__ void ldm_x4(uint32_t* r, uint32_t addr) {
    asm volatile("ldmatrix.sync.aligned.m8n8.x4.shared.b16 {%0,%1,%2,%3}, [%4];"
        : "=r"(r[0]), "=r"(r[1]), "=r"(r[2]), "=r"(r[3]) : "r"(addr));
}
__device__ __forceinline__ void mma_bf16(float* c, const uint32_t* a, const uint32_t* b) {
    asm volatile("mma.sync.aligned.m16n8k16.row.col.f32.bf16.bf16.f32 "
        "{%0,%1,%2,%3}, {%4,%5,%6,%7}, {%8,%9}, {%0,%1,%2,%3};"
        : "+f"(c[0]), "+f"(c[1]), "+f"(c[2]), "+f"(c[3])
        : "r"(a[0]), "r"(a[1]), "r"(a[2]), "r"(a[3]), "r"(b[0]), "r"(b[1]));
}
#define CP_ASYNC16(sm, gm) \
    asm volatile("cp.async.cg.shared.global [%0], [%1], 16;" :: "r"(sm), "l"(gm) : "memory")
#define CP_COMMIT() asm volatile("cp.async.commit_group;" ::: "memory")
#define CP_WAIT0()  asm volatile("cp.async.wait_group 0;" ::: "memory")

__device__ __forceinline__ uint32_t pack_bf2(float a, float b) {
    __nv_bfloat162 t = __floats2bfloat162_rn(a, b);
    return *reinterpret_cast<uint32_t*>(&t);
}

// ---------------------------------------------------------------------------
// Pre-pass: W fp32 [1024][64] x3  ->  W^T hi/lo bf16 [192][1024]
// One block per output row n; threads stride over k -> coalesced bf16 stores.
// ---------------------------------------------------------------------------
__global__ __launch_bounds__(256)
void conv_w(const float* __restrict__ Wq,
            const float* __restrict__ Wk,
            const float* __restrict__ Wv) {
    const int n = blockIdx.x;        // 0..191
    const float* W = (n < 64) ? Wq : ((n < 128) ? Wk : Wv);
    const int nc = n & 63;
    __nv_bfloat16* hd = g_wt_hi + (size_t)n * CDIM;
    __nv_bfloat16* ld = g_wt_lo + (size_t)n * CDIM;
    #pragma unroll
    for (int kk = 0; kk < 4; kk++) {
        int k = kk * 256 + threadIdx.x;
        float v = __ldg(W + (size_t)k * 64 + nc);
        __nv_bfloat16 h = __float2bfloat16(v);
        hd[k] = h;
        ld[k] = __float2bfloat16(v - __bfloat162float(h));
    }
}

// ---------------------------------------------------------------------------
// HMMA GEMM: g_qkv[m][0..191] = x[m][:] @ [Wq|Wk|Wv], bf16 2-term split.
// BM=128, N=192, BK=32, 8 warps (4m x 2n), warp tile 32x96.
// MMAs issued in 3 passes (hi*hi, lo*hi, hi*lo) -> same-acc reuse distance 24.
// ---------------------------------------------------------------------------
#define BM   128
#define BK   32
#define NC   (CDIM / BK)      // 32 chunks
#define SA   40               // smem row stride in halfs (80 B, conflict-free)
#define OFF_AHI 0
#define OFF_ALO (BM * SA * 2)                       // 10240
#define OFF_BHI (2 * BM * SA * 2)                   // 20480
#define OFF_BLO (OFF_BHI + QKVW * SA * 2)           // 35840
#define STAGE   (OFF_BLO + QKVW * SA * 2)           // 51200
#define GEMM_SMEM (2 * STAGE)                       // 102400

__global__ __launch_bounds__(256, 1)
void qkv_gemm_mma(const float* __restrict__ x) {
    extern __shared__ char sm[];
    const uint32_t smb = smem_u32(sm);

    const int tid  = threadIdx.x;
    const int wid  = tid >> 5;
    const int lane = tid & 31;
    const int wm   = wid >> 1;       // 0..3
    const int wn   = wid & 1;        // 0..1
    const int m0   = blockIdx.x * BM;

    float acc[2][12][4];
    #pragma unroll
    for (int mt = 0; mt < 2; mt++)
        #pragma unroll
        for (int nt = 0; nt < 12; nt++)
            #pragma unroll
            for (int q = 0; q < 4; q++) acc[mt][nt][q] = 0.f;

    // ldmatrix lane addressing
    const int a_row  = (lane & 15);
    const int a_col  = (lane >> 4) * 8;
    const int b_rowo = ((lane >> 4) << 3) + (lane & 7);
    const int b_col  = ((lane >> 3) & 1) * 8;

    // global-load lane mapping
    const int xrow = tid >> 3, xq4 = tid & 7;          // + l*32 rows
    const int bn = tid >> 2, bu = tid & 3;             // + l*64 rows

    float4 xf[4];

    // ---- prologue: chunk 0 ----
    {
        #pragma unroll
        for (int l = 0; l < 4; l++)
            xf[l] = *reinterpret_cast<const float4*>(
                x + (size_t)(m0 + xrow + l * 32) * CDIM + xq4 * 4);
        #pragma unroll
        for (int l = 0; l < 3; l++) {
            int n = bn + l * 64;
            uint32_t so = (uint32_t)(n * SA + bu * 8) * 2;
            CP_ASYNC16(smb + OFF_BHI + so, g_wt_hi + (size_t)n * CDIM + bu * 8);
            CP_ASYNC16(smb + OFF_BLO + so, g_wt_lo + (size_t)n * CDIM + bu * 8);
        }
        CP_COMMIT();
        #pragma unroll
        for (int l = 0; l < 4; l++) {
            int row = xrow + l * 32;
            float hx = __bfloat162float(__float2bfloat16(xf[l].x));
            float hy = __bfloat162float(__float2bfloat16(xf[l].y));
            float hz = __bfloat162float(__float2bfloat16(xf[l].z));
            float hw = __bfloat162float(__float2bfloat16(xf[l].w));
            uint2 hp = make_uint2(pack_bf2(xf[l].x, xf[l].y), pack_bf2(xf[l].z, xf[l].w));
            uint2 lp = make_uint2(pack_bf2(xf[l].x - hx, xf[l].y - hy),
                                  pack_bf2(xf[l].z - hz, xf[l].w - hw));
            uint32_t so = (uint32_t)(row * SA + xq4 * 4) * 2;
            *reinterpret_cast<uint2*>(sm + OFF_AHI + so) = hp;
            *reinterpret_cast<uint2*>(sm + OFF_ALO + so) = lp;
        }
        CP_WAIT0();
        __syncthreads();
    }

    for (int c = 0; c < NC; c++) {
        const int s = c & 1;
        const uint32_t st = smb + s * STAGE;
        const bool more = (c + 1 < NC);

        // ---- prefetch chunk c+1 ----
        if (more) {
            const int k1 = (c + 1) * BK;
            #pragma unroll
            for (int l = 0; l < 4; l++)
                xf[l] = *reinterpret_cast<const float4*>(
                    x + (size_t)(m0 + xrow + l * 32) * CDIM + k1 + xq4 * 4);
            const uint32_t stn = smb + (s ^ 1) * STAGE;
            #pragma unroll
            for (int l = 0; l < 3; l++) {
                int n = bn + l * 64;
                uint32_t so = (uint32_t)(n * SA + bu * 8) * 2;
                CP_ASYNC16(stn + OFF_BHI + so, g_wt_hi + (size_t)n * CDIM + k1 + bu * 8);
                CP_ASYNC16(stn + OFF_BLO + so, g_wt_lo + (size_t)n * CDIM + k1 + bu * 8);
            }
            CP_COMMIT();
        }

        // ---- compute chunk c ----
        #pragma unroll
        for (int ks = 0; ks < 2; ks++) {
            const int k0 = ks * 16;
            uint32_t ahi[2][4], alo[2][4], bf[6][4];
            #pragma unroll
            for (int mt = 0; mt < 2; mt++) {
                uint32_t ao = (uint32_t)((wm * 32 + mt * 16 + a_row) * SA + k0 + a_col) * 2;
                ldm_x4(ahi[mt], st + OFF_AHI + ao);
                ldm_x4(alo[mt], st + OFF_ALO + ao);
            }
            #pragma unroll
            for (int g = 0; g < 6; g++) {
                uint32_t bo = (uint32_t)((wn * 96 + g * 16 + b_rowo) * SA + k0 + b_col) * 2;
                ldm_x4(bf[g], st + OFF_BHI + bo);
            }
            // pass 1: hi * hi  (24 independent MMAs)
            #pragma unroll
            for (int mt = 0; mt < 2; mt++)
                #pragma unroll
                for (int g = 0; g < 6; g++) {
                    mma_bf16(acc[mt][2 * g],     ahi[mt], &bf[g][0]);
                    mma_bf16(acc[mt][2 * g + 1], ahi[mt], &bf[g][2]);
                }
            // pass 2: lo * hi  (same-acc distance 24)
            #pragma unroll
            for (int mt = 0; mt < 2; mt++)
                #pragma unroll
                for (int g = 0; g < 6; g++) {
                    mma_bf16(acc[mt][2 * g],     alo[mt], &bf[g][0]);
                    mma_bf16(acc[mt][2 * g + 1], alo[mt], &bf[g][2]);
                }
            // pass 3: hi * lo
            #pragma unroll
            for (int g = 0; g < 6; g++) {
                uint32_t bo = (uint32_t)((wn * 96 + g * 16 + b_rowo) * SA + k0 + b_col) * 2;
                ldm_x4(bf[g], st + OFF_BLO + bo);
            }
            #pragma unroll
            for (int mt = 0; mt < 2; mt++)
                #pragma unroll
                for (int g = 0; g < 6; g++) {
                    mma_bf16(acc[mt][2 * g],     ahi[mt], &bf[g][0]);
                    mma_bf16(acc[mt][2 * g + 1], ahi[mt], &bf[g][2]);
                }
        }

        // ---- store prefetched x into next stage ----
        if (more) {
            char* stn = sm + (s ^ 1) * STAGE;
            #pragma unroll
            for (int l = 0; l < 4; l++) {
                int row = xrow + l * 32;
                float hx = __bfloat162float(__float2bfloat16(xf[l].x));
                float hy = __bfloat162float(__float2bfloat16(xf[l].y));
                float hz = __bfloat162float(__float2bfloat16(xf[l].z));
                float hw = __bfloat162float(__float2bfloat16(xf[l].w));
                uint2 hp = make_uint2(pack_bf2(xf[l].x, xf[l].y), pack_bf2(xf[l].z, xf[l].w));
                uint2 lp = make_uint2(pack_bf2(xf[l].x - hx, xf[l].y - hy),
                                      pack_bf2(xf[l].z - hz, xf[l].w - hw));
                uint32_t so = (uint32_t)(row * SA + xq4 * 4) * 2;
                *reinterpret_cast<uint2*>(stn + OFF_AHI + so) = hp;
                *reinterpret_cast<uint2*>(stn + OFF_ALO + so) = lp;
            }
            CP_WAIT0();
            __syncthreads();
        }
    }

    // ---- epilogue ----
    const int grp = lane >> 2, tig = lane & 3;
    #pragma unroll
    for (int mt = 0; mt < 2; mt++) {
        const int row = m0 + wm * 32 + mt * 16 + grp;
        #pragma unroll
        for (int nt = 0; nt < 12; nt++) {
            const int col = wn * 96 + nt * 8 + tig * 2;
            *reinterpret_cast<float2*>(g_qkv + (size_t)row * QKVW + col) =
                make_float2(acc[mt][nt][0], acc[mt][nt][1]);
            *reinterpret_cast<float2*>(g_qkv + (size_t)(row + 8) * QKVW + col) =
                make_float2(acc[mt][nt][2], acc[mt][nt][3]);
        }
    }
}

// ---------------------------------------------------------------------------
// Attention: 128 queries/block, 2 lanes per query (dim halves), k/v in smem.
// smem row stride 66 words, half offset 33 -> conflict-free scalar LDS.
// ---------------------------------------------------------------------------
#define AT_ROWS 144
#define AT_STRIDE 66
#define ATT_SMEM (2 * AT_ROWS * AT_STRIDE * 4)   // 76032

__global__ __launch_bounds__(256)
void attn2(float* __restrict__ out) {
    extern __shared__ float smf[];
    float* const ks = smf;
    float* const vs = smf + AT_ROWS * AT_STRIDE;

    const int tid = threadIdx.x;
    const int b  = blockIdx.x >> 6;
    const int i0 = (blockIdx.x & 63) * 128;

    #pragma unroll
    for (int l = 0; l < 9; l++) {
        int lin = l * 256 + tid;           // 0..2303
        int idx = lin >> 4, c4 = lin & 15;
        int j = i0 - 16 + idx;
        float4 kv = make_float4(0.f, 0.f, 0.f, 0.f);
        float4 vv = make_float4(0.f, 0.f, 0.f, 0.f);
        if (j >= 0) {
            const float* src = g_qkv + (size_t)(b * SEQ + j) * QKVW;
            kv = *reinterpret_cast<const float4*>(src + HDIM + c4 * 4);
            vv = *reinterpret_cast<const float4*>(src + 2 * HDIM + c4 * 4);
        }
        int d = c4 * 4;
        int w = idx * AT_STRIDE + (d < 32 ? d : 33 + (d - 32));
        ks[w + 0] = kv.x; ks[w + 1] = kv.y; ks[w + 2] = kv.z; ks[w + 3] = kv.w;
        vs[w + 0] = vv.x; vs[w + 1] = vv.y; vs[w + 2] = vv.z; vs[w + 3] = vv.w;
    }

    const int lane = tid & 31;
    const int wrp = tid >> 5;
    const int qi = wrp * 16 + (lane & 15);   // 0..127
    const int h = lane >> 4;
    const int d0 = h * 32;
    const int i = i0 + qi;
    const size_t grow = (size_t)(b * SEQ + i);

    float q[32];
    {
        const float* qp = g_qkv + grow * QKVW + d0;
        #pragma unroll
        for (int cc = 0; cc < 32; cc += 4) {
            float4 t = *reinterpret_cast<const float4*>(qp + cc);
            q[cc] = t.x; q[cc + 1] = t.y; q[cc + 2] = t.z; q[cc + 3] = t.w;
        }
    }
    __syncthreads();

    float sc[17];
    float mx = -1e30f;
    #pragma unroll
    for (int t = 0; t < 17; t++) {
        const float* kr = ks + (qi + t) * AT_STRIDE + h * 33;
        float p0 = 0.f, p1 = 0.f, p2 = 0.f, p3 = 0.f;
        #pragma unroll
        for (int cc = 0; cc < 32; cc += 4) {
            p0 = fmaf(q[cc + 0], kr[cc + 0], p0);
            p1 = fmaf(q[cc + 1], kr[cc + 1], p1);
            p2 = fmaf(q[cc + 2], kr[cc + 2], p2);
            p3 = fmaf(q[cc + 3], kr[cc + 3], p3);
        }
        float p = (p0 + p1) + (p2 + p3);
        p += __shfl_xor_sync(0xffffffffu, p, 16);
        float d = (i - 16 + t >= 0) ? p * 0.125f : -1e30f;
        sc[t] = d;
        mx = fmaxf(mx, d);
    }

    float den = 0.f;
    #pragma unroll
    for (int t = 0; t < 17; t++) { sc[t] = __expf(sc[t] - mx); den += sc[t]; }
    const float inv = 1.0f / den;

    float* op = out + grow * HDIM + d0;
    #pragma unroll
    for (int cb = 0; cb < 32; cb += 4) {
        float a0 = 0.f, a1 = 0.f, a2 = 0.f, a3 = 0.f;
        #pragma unroll
        for (int t = 0; t < 17; t++) {
            const float* vr = vs + (qi + t) * AT_STRIDE + h * 33 + cb;
            a0 = fmaf(sc[t], vr[0], a0);
            a1 = fmaf(sc[t], vr[1], a1);
            a2 = fmaf(sc[t], vr[2], a2);
            a3 = fmaf(sc[t], vr[3], a3);
        }
        *reinterpret_cast<float4*>(op + cb) =
            make_float4(a0 * inv, a1 * inv, a2 * inv, a3 * inv);
    }
}

// ---------------------------------------------------------------------------
extern "C" void kernel_launch(void* const* d_in, const int* in_sizes, int n_in,
                              void* d_out, int out_size)
{
    const float* x  = (const float*)d_in[0];
    const float* Wq = (const float*)d_in[1];
    const float* Wk = (const float*)d_in[2];
    const float* Wv = (const float*)d_in[3];
    float* out = (float*)d_out;

    cudaFuncSetAttribute(qkv_gemm_mma, cudaFuncAttributeMaxDynamicSharedMemorySize, GEMM_SMEM);
    cudaFuncSetAttribute(attn2,        cudaFuncAttributeMaxDynamicSharedMemorySize, ATT_SMEM);

    conv_w<<<QKVW, 256>>>(Wq, Wk, Wv);
    qkv_gemm_mma<<<NROWS / BM, 256, GEMM_SMEM>>>(x);
    attn2<<<128, 256, ATT_SMEM>>>(out);
}

// round 5
// speedup vs baseline: 3.2832x; 1.2646x over previous
#include <cuda_runtime.h>
#include <cuda_bf16.h>
#include <cuda_fp16.h>
#include <cstdint>

#define BATCH 2
#define SEQ   8192
#define CDIM  1024
#define HDIM  64
#define NROWS (BATCH * SEQ)   // 16384
#define QKVW  (3 * HDIM)      // 192
#define WSCALE 64.0f
#define WSCALE_INV (1.0f / 64.0f)

// ---- device scratch (no allocations) --------------------------------------
__device__ float  g_qkv[(size_t)NROWS * QKVW];   // 12 MB  q|k|v per row
__device__ __half g_wh[QKVW * CDIM];             // (64*W)^T hi  [192][1024]
__device__ __half g_wl[QKVW * CDIM];             // (64*W)^T lo

// ---- helpers ----------------------------------------------------------------
__device__ __forceinline__ uint32_t smem_u32(const void* p) {
    uint32_t a;
    asm("{ .reg .u64 t; cvta.to.shared.u64 t, %1; cvt.u32.u64 %0, t; }"
        : "=r"(a) : "l"(p));
    return a;
}
__device__ __forceinline__ void ldm_x4(uint32_t* r, uint32_t addr) {
    asm volatile("ldmatrix.sync.aligned.m8n8.x4.shared.b16 {%0,%1,%2,%3}, [%4];"
        : "=r"(r[0]), "=r"(r[1]), "=r"(r[2]), "=r"(r[3]) : "r"(addr));
}
__device__ __forceinline__ void mma_f16(float* c, const uint32_t* a, const uint32_t* b) {
    asm volatile("mma.sync.aligned.m16n8k16.row.col.f32.f16.f16.f32 "
        "{%0,%1,%2,%3}, {%4,%5,%6,%7}, {%8,%9}, {%0,%1,%2,%3};"
        : "+f"(c[0]), "+f"(c[1]), "+f"(c[2]), "+f"(c[3])
        : "r"(a[0]), "r"(a[1]), "r"(a[2]), "r"(a[3]), "r"(b[0]), "r"(b[1]));
}
#define CP_ASYNC16(sm, gm) \
    asm volatile("cp.async.cg.shared.global [%0], [%1], 16;" :: "r"(sm), "l"(gm) : "memory")
#define CP_COMMIT() asm volatile("cp.async.commit_group;" ::: "memory")
#define CP_WAIT0()  asm volatile("cp.async.wait_group 0;" ::: "memory")

__device__ __forceinline__ uint32_t pack_h2(float a, float b) {
    __half2 t = __floats2half2_rn(a, b);
    return *reinterpret_cast<uint32_t*>(&t);
}

// ---------------------------------------------------------------------------
// Pre-pass: W fp32 [1024][64] x3  ->  (64*W)^T hi/lo fp16 [192][1024]
// Tiled transpose: coalesced loads and stores. grid = 3 mats x 16 k-tiles.
// ---------------------------------------------------------------------------
__global__ __launch_bounds__(256)
void conv_w(const float* __restrict__ Wq,
            const float* __restrict__ Wk,
            const float* __restrict__ Wv) {
    __shared__ float ts[64][65];
    const int mat = blockIdx.x >> 4;         // 0..2
    const int k0  = (blockIdx.x & 15) * 64;  // k tile
    const float* W = (mat == 0) ? Wq : ((mat == 1) ? Wk : Wv);
    const int tid = threadIdx.x;

    const int ln = tid & 63, lk = tid >> 6;  // load: n fastest -> coalesced
    #pragma unroll
    for (int i = 0; i < 16; i++)
        ts[lk + i * 4][ln] = W[(size_t)(k0 + lk + i * 4) * 64 + ln];
    __syncthreads();

    const int n = tid >> 2, kq = (tid & 3) * 16;
    __half* hd = g_wh + (size_t)(mat * 64 + n) * CDIM + k0 + kq;
    __half* ld = g_wl + (size_t)(mat * 64 + n) * CDIM + k0 + kq;
    #pragma unroll
    for (int j = 0; j < 16; j++) {
        float v = ts[kq + j][n] * WSCALE;
        __half h = __float2half_rn(v);
        hd[j] = h;
        ld[j] = __float2half_rn(v - __half2float(h));
    }
}

// ---------------------------------------------------------------------------
// HMMA GEMM: g_qkv[m][0..191] = x[m][:] @ [Wq|Wk|Wv]
// fp16 2-term: xh*(wh+wl) = xh*(64W) to 2^-22, epilogue * 1/64.
// BM=128, N=192, BK=64, 8 warps (4m x 2n), warp tile 32x96.
// ---------------------------------------------------------------------------
#define BM   128
#define BK   64
#define NCH  (CDIM / BK)      // 16 chunks
#define SA   72               // smem row stride in halfs (144 B, ldmatrix conflict-free)
#define OFF_A  0
#define OFF_BH (BM * SA * 2)                       // 18432
#define OFF_BL (OFF_BH + QKVW * SA * 2)            // 46080
#define STAGE  (OFF_BL + QKVW * SA * 2)            // 73728
#define GEMM_SMEM (2 * STAGE)                      // 147456

__global__ __launch_bounds__(256, 1)
void qkv_gemm_mma(const float* __restrict__ x) {
    extern __shared__ char sm[];
    const uint32_t smb = smem_u32(sm);

    const int tid  = threadIdx.x;
    const int wid  = tid >> 5;
    const int lane = tid & 31;
    const int wm   = wid >> 1;       // 0..3
    const int wn   = wid & 1;        // 0..1
    const int m0   = blockIdx.x * BM;

    float acc[2][12][4];
    #pragma unroll
    for (int mt = 0; mt < 2; mt++)
        #pragma unroll
        for (int nt = 0; nt < 12; nt++)
            #pragma unroll
            for (int q = 0; q < 4; q++) acc[mt][nt][q] = 0.f;

    // ldmatrix lane addressing
    const int a_row  = (lane & 15);
    const int a_col  = (lane >> 4) * 8;
    const int b_rowo = ((lane >> 4) << 3) + (lane & 7);
    const int b_col  = ((lane >> 3) & 1) * 8;

    // global-load lane mapping
    const int xrow = tid >> 3, xq4b = tid & 7;     // x: 8 threads per 128B row-chunk
    const int bn = tid >> 3, bu = tid & 7;         // B: idx over rows/16B units

    float4 xf[8];

    // convert + store x tile into a stage
    auto store_x = [&](char* stp) {
        #pragma unroll
        for (int l = 0; l < 8; l++) {
            int row = xrow + (l & 3) * 32;
            int k4  = xq4b + (l >> 2) * 8;
            uint2 hp = make_uint2(pack_h2(xf[l].x, xf[l].y), pack_h2(xf[l].z, xf[l].w));
            *reinterpret_cast<uint2*>(stp + OFF_A + (uint32_t)(row * SA + k4 * 4) * 2) = hp;
        }
    };
    auto load_x = [&](int k0) {
        #pragma unroll
        for (int l = 0; l < 8; l++) {
            int row = xrow + (l & 3) * 32;
            int k4  = xq4b + (l >> 2) * 8;
            xf[l] = *reinterpret_cast<const float4*>(
                x + (size_t)(m0 + row) * CDIM + k0 + k4 * 4);
        }
    };
    auto issue_b = [&](uint32_t stn, int k0) {
        #pragma unroll
        for (int l = 0; l < 6; l++) {
            int idx = l * 256 + tid;           // 0..1535
            int n = idx >> 3, u = idx & 7;
            uint32_t so = (uint32_t)(n * SA) * 2 + u * 16;
            CP_ASYNC16(stn + OFF_BH + so, g_wh + (size_t)n * CDIM + k0 + u * 8);
            CP_ASYNC16(stn + OFF_BL + so, g_wl + (size_t)n * CDIM + k0 + u * 8);
        }
        CP_COMMIT();
    };
    (void)bn; (void)bu;

    // ---- prologue: chunk 0 ----
    load_x(0);
    issue_b(smb, 0);
    store_x(sm);
    CP_WAIT0();
    __syncthreads();

    for (int c = 0; c < NCH; c++) {
        const int s = c & 1;
        const uint32_t st = smb + s * STAGE;
        const bool more = (c + 1 < NCH);

        if (more) {
            load_x((c + 1) * BK);
            issue_b(smb + (s ^ 1) * STAGE, (c + 1) * BK);
        }

        // ---- compute chunk c: 4 k-steps ----
        #pragma unroll
        for (int ks = 0; ks < 4; ks++) {
            const int k0h = ks * 16;
            uint32_t ah[2][4], bf[6][4];
            #pragma unroll
            for (int mt = 0; mt < 2; mt++) {
                uint32_t ao = (uint32_t)((wm * 32 + mt * 16 + a_row) * SA + k0h + a_col) * 2;
                ldm_x4(ah[mt], st + OFF_A + ao);
            }
            #pragma unroll
            for (int g = 0; g < 6; g++) {
                uint32_t bo = (uint32_t)((wn * 96 + g * 16 + b_rowo) * SA + k0h + b_col) * 2;
                ldm_x4(bf[g], st + OFF_BH + bo);
            }
            #pragma unroll
            for (int mt = 0; mt < 2; mt++)
                #pragma unroll
                for (int g = 0; g < 6; g++) {
                    mma_f16(acc[mt][2 * g],     ah[mt], &bf[g][0]);
                    mma_f16(acc[mt][2 * g + 1], ah[mt], &bf[g][2]);
                }
            #pragma unroll
            for (int g = 0; g < 6; g++) {
                uint32_t bo = (uint32_t)((wn * 96 + g * 16 + b_rowo) * SA + k0h + b_col) * 2;
                ldm_x4(bf[g], st + OFF_BL + bo);
            }
            #pragma unroll
            for (int mt = 0; mt < 2; mt++)
                #pragma unroll
                for (int g = 0; g < 6; g++) {
                    mma_f16(acc[mt][2 * g],     ah[mt], &bf[g][0]);
                    mma_f16(acc[mt][2 * g + 1], ah[mt], &bf[g][2]);
                }
        }

        if (more) {
            store_x(sm + (s ^ 1) * STAGE);
            CP_WAIT0();
            __syncthreads();
        }
    }

    // ---- epilogue (scale by 1/64) ----
    const int grp = lane >> 2, tig = lane & 3;
    #pragma unroll
    for (int mt = 0; mt < 2; mt++) {
        const int row = m0 + wm * 32 + mt * 16 + grp;
        #pragma unroll
        for (int nt = 0; nt < 12; nt++) {
            const int col = wn * 96 + nt * 8 + tig * 2;
            *reinterpret_cast<float2*>(g_qkv + (size_t)row * QKVW + col) =
                make_float2(acc[mt][nt][0] * WSCALE_INV, acc[mt][nt][1] * WSCALE_INV);
            *reinterpret_cast<float2*>(g_qkv + (size_t)(row + 8) * QKVW + col) =
                make_float2(acc[mt][nt][2] * WSCALE_INV, acc[mt][nt][3] * WSCALE_INV);
        }
    }
}

// ---------------------------------------------------------------------------
// Attention: 128 queries/block, 2 lanes per query (dim halves), k/v in smem.
// ---------------------------------------------------------------------------
#define AT_ROWS 144
#define AT_STRIDE 66
#define ATT_SMEM (2 * AT_ROWS * AT_STRIDE * 4)   // 76032

__global__ __launch_bounds__(256)
void attn2(float* __restrict__ out) {
    extern __shared__ float smf[];
    float* const ks = smf;
    float* const vs = smf + AT_ROWS * AT_STRIDE;

    const int tid = threadIdx.x;
    const int b  = blockIdx.x >> 6;
    const int i0 = (blockIdx.x & 63) * 128;

    #pragma unroll
    for (int l = 0; l < 9; l++) {
        int lin = l * 256 + tid;           // 0..2303
        int idx = lin >> 4, c4 = lin & 15;
        int j = i0 - 16 + idx;
        float4 kv = make_float4(0.f, 0.f, 0.f, 0.f);
        float4 vv = make_float4(0.f, 0.f, 0.f, 0.f);
        if (j >= 0) {
            const float* src = g_qkv + (size_t)(b * SEQ + j) * QKVW;
            kv = *reinterpret_cast<const float4*>(src + HDIM + c4 * 4);
            vv = *reinterpret_cast<const float4*>(src + 2 * HDIM + c4 * 4);
        }
        int d = c4 * 4;
        int w = idx * AT_STRIDE + (d < 32 ? d : 33 + (d - 32));
        ks[w + 0] = kv.x; ks[w + 1] = kv.y; ks[w + 2] = kv.z; ks[w + 3] = kv.w;
        vs[w + 0] = vv.x; vs[w + 1] = vv.y; vs[w + 2] = vv.z; vs[w + 3] = vv.w;
    }

    const int lane = tid & 31;
    const int wrp = tid >> 5;
    const int qi = wrp * 16 + (lane & 15);   // 0..127
    const int h = lane >> 4;
    const int d0 = h * 32;
    const int i = i0 + qi;
    const size_t grow = (size_t)(b * SEQ + i);

    float q[32];
    {
        const float* qp = g_qkv + grow * QKVW + d0;
        #pragma unroll
        for (int cc = 0; cc < 32; cc += 4) {
            float4 t = *reinterpret_cast<const float4*>(qp + cc);
            q[cc] = t.x; q[cc + 1] = t.y; q[cc + 2] = t.z; q[cc + 3] = t.w;
        }
    }
    __syncthreads();

    float sc[17];
    float mx = -1e30f;
    #pragma unroll
    for (int t = 0; t < 17; t++) {
        const float* kr = ks + (qi + t) * AT_STRIDE + h * 33;
        float p0 = 0.f, p1 = 0.f, p2 = 0.f, p3 = 0.f;
        #pragma unroll
        for (int cc = 0; cc < 32; cc += 4) {
            p0 = fmaf(q[cc + 0], kr[cc + 0], p0);
            p1 = fmaf(q[cc + 1], kr[cc + 1], p1);
            p2 = fmaf(q[cc + 2], kr[cc + 2], p2);
            p3 = fmaf(q[cc + 3], kr[cc + 3], p3);
        }
        float p = (p0 + p1) + (p2 + p3);
        p += __shfl_xor_sync(0xffffffffu, p, 16);
        float d = (i - 16 + t >= 0) ? p * 0.125f : -1e30f;
        sc[t] = d;
        mx = fmaxf(mx, d);
    }

    float den = 0.f;
    #pragma unroll
    for (int t = 0; t < 17; t++) { sc[t] = __expf(sc[t] - mx); den += sc[t]; }
    const float inv = 1.0f / den;

    float* op = out + grow * HDIM + d0;
    #pragma unroll
    for (int cb = 0; cb < 32; cb += 4) {
        float a0 = 0.f, a1 = 0.f, a2 = 0.f, a3 = 0.f;
        #pragma unroll
        for (int t = 0; t < 17; t++) {
            const float* vr = vs + (qi + t) * AT_STRIDE + h * 33 + cb;
            a0 = fmaf(sc[t], vr[0], a0);
            a1 = fmaf(sc[t], vr[1], a1);
            a2 = fmaf(sc[t], vr[2], a2);
            a3 = fmaf(sc[t], vr[3], a3);
        }
        *reinterpret_cast<float4*>(op + cb) =
            make_float4(a0 * inv, a1 * inv, a2 * inv, a3 * inv);
    }
}

// ---------------------------------------------------------------------------
extern "C" void kernel_launch(void* const* d_in, const int* in_sizes, int n_in,
                              void* d_out, int out_size)
{
    const float* x  = (const float*)d_in[0];
    const float* Wq = (const float*)d_in[1];
    const float* Wk = (const float*)d_in[2];
    const float* Wv = (const float*)d_in[3];
    float* out = (float*)d_out;

    cudaFuncSetAttribute(qkv_gemm_mma, cudaFuncAttributeMaxDynamicSharedMemorySize, GEMM_SMEM);
    cudaFuncSetAttribute(attn2,        cudaFuncAttributeMaxDynamicSharedMemorySize, ATT_SMEM);

    conv_w<<<48, 256>>>(Wq, Wk, Wv);
    qkv_gemm_mma<<<NROWS / BM, 256, GEMM_SMEM>>>(x);
    attn2<<<128, 256, ATT_SMEM>>>(out);
}

// round 6
// speedup vs baseline: 4.8794x; 1.4862x over previous
#include <cuda_runtime.h>
#include <cuda_fp16.h>
#include <cstdint>

#define BATCH 2
#define SEQ   8192
#define CDIM  1024
#define HDIM  64
#define NROWS (BATCH * SEQ)   // 16384
#define QKVW  (3 * HDIM)      // 192

// ---- device scratch (no allocations) --------------------------------------
__device__ float  g_qkv[(size_t)NROWS * QKVW];   // 12 MB  q|k|v per row
__device__ __half g_wh[QKVW * CDIM];             // W^T fp16  [192][1024]

// ---- helpers ----------------------------------------------------------------
__device__ __forceinline__ uint32_t smem_u32(const void* p) {
    uint32_t a;
    asm("{ .reg .u64 t; cvta.to.shared.u64 t, %1; cvt.u32.u64 %0, t; }"
        : "=r"(a) : "l"(p));
    return a;
}
__device__ __forceinline__ void ldm_x4(uint32_t* r, uint32_t addr) {
    asm volatile("ldmatrix.sync.aligned.m8n8.x4.shared.b16 {%0,%1,%2,%3}, [%4];"
        : "=r"(r[0]), "=r"(r[1]), "=r"(r[2]), "=r"(r[3]) : "r"(addr));
}
__device__ __forceinline__ void mma_f16(float* c, const uint32_t* a, const uint32_t* b) {
    asm volatile("mma.sync.aligned.m16n8k16.row.col.f32.f16.f16.f32 "
        "{%0,%1,%2,%3}, {%4,%5,%6,%7}, {%8,%9}, {%0,%1,%2,%3};"
        : "+f"(c[0]), "+f"(c[1]), "+f"(c[2]), "+f"(c[3])
        : "r"(a[0]), "r"(a[1]), "r"(a[2]), "r"(a[3]), "r"(b[0]), "r"(b[1]));
}
#define CP_ASYNC16(sm, gm) \
    asm volatile("cp.async.cg.shared.global [%0], [%1], 16;" :: "r"(sm), "l"(gm) : "memory")
#define CP_COMMIT() asm volatile("cp.async.commit_group;" ::: "memory")
#define CP_WAIT0()  asm volatile("cp.async.wait_group 0;" ::: "memory")

__device__ __forceinline__ uint32_t pack_h2(float a, float b) {
    __half2 t = __floats2half2_rn(a, b);
    return *reinterpret_cast<uint32_t*>(&t);
}

// ---------------------------------------------------------------------------
// Pre-pass: W fp32 [1024][64] x3  ->  W^T fp16 [192][1024]
// 192 blocks: (mat, 16-row k tile). Coalesced load, smem transpose, store.
// ---------------------------------------------------------------------------
__global__ __launch_bounds__(256)
void conv_w(const float* __restrict__ Wq,
            const float* __restrict__ Wk,
            const float* __restrict__ Wv) {
    __shared__ float ts[16][65];
    const int mat = blockIdx.x >> 6;          // 0..2
    const int k0  = (blockIdx.x & 63) * 16;   // k tile
    const float* W = (mat == 0) ? Wq : ((mat == 1) ? Wk : Wv);
    const int tid = threadIdx.x;

    // load 16 k-rows x 64 n, coalesced (4 floats/thread)
    const int ln = tid & 63, lk = tid >> 6;
    #pragma unroll
    for (int i = 0; i < 4; i++)
        ts[lk + i * 4][ln] = W[(size_t)(k0 + lk + i * 4) * 64 + ln];
    __syncthreads();

    // store: thread -> (n = tid>>2, 4 k values), 8B contiguous per thread
    const int n = tid >> 2, kq = (tid & 3) * 4;
    __half* hd = g_wh + (size_t)(mat * 64 + n) * CDIM + k0 + kq;
    __half2 a = __floats2half2_rn(ts[kq + 0][n], ts[kq + 1][n]);
    __half2 b = __floats2half2_rn(ts[kq + 2][n], ts[kq + 3][n]);
    *reinterpret_cast<__half2*>(hd)     = a;
    *reinterpret_cast<__half2*>(hd + 2) = b;
}

// ---------------------------------------------------------------------------
// HMMA GEMM: g_qkv[m][0..191] = x[m][:] @ [Wq|Wk|Wv], single-term fp16.
// BM=128, N=192, BK=64, 8 warps (4m x 2n), warp tile 32x96.
// ---------------------------------------------------------------------------
#define BM   128
#define BK   64
#define NCH  (CDIM / BK)      // 16 chunks
#define SA   72               // smem row stride in halfs (144 B)
#define OFF_A  0
#define OFF_BH (BM * SA * 2)                       // 18432
#define STAGE  (OFF_BH + QKVW * SA * 2)            // 46080
#define GEMM_SMEM (2 * STAGE)                      // 92160

__global__ __launch_bounds__(256, 1)
void qkv_gemm_mma(const float* __restrict__ x) {
    extern __shared__ char sm[];
    const uint32_t smb = smem_u32(sm);

    const int tid  = threadIdx.x;
    const int wid  = tid >> 5;
    const int lane = tid & 31;
    const int wm   = wid >> 1;       // 0..3
    const int wn   = wid & 1;        // 0..1
    const int m0   = blockIdx.x * BM;

    float acc[2][12][4];
    #pragma unroll
    for (int mt = 0; mt < 2; mt++)
        #pragma unroll
        for (int nt = 0; nt < 12; nt++)
            #pragma unroll
            for (int q = 0; q < 4; q++) acc[mt][nt][q] = 0.f;

    const int a_row  = (lane & 15);
    const int a_col  = (lane >> 4) * 8;
    const int b_rowo = ((lane >> 4) << 3) + (lane & 7);
    const int b_col  = ((lane >> 3) & 1) * 8;

    const int xrow = tid >> 3, xq4b = tid & 7;

    float4 xf[8];

    auto load_x = [&](int k0) {
        #pragma unroll
        for (int l = 0; l < 8; l++) {
            int row = xrow + (l & 3) * 32;
            int k4  = xq4b + (l >> 2) * 8;
            xf[l] = *reinterpret_cast<const float4*>(
                x + (size_t)(m0 + row) * CDIM + k0 + k4 * 4);
        }
    };
    auto store_x = [&](char* stp) {
        #pragma unroll
        for (int l = 0; l < 8; l++) {
            int row = xrow + (l & 3) * 32;
            int k4  = xq4b + (l >> 2) * 8;
            uint2 hp = make_uint2(pack_h2(xf[l].x, xf[l].y), pack_h2(xf[l].z, xf[l].w));
            *reinterpret_cast<uint2*>(stp + OFF_A + (uint32_t)(row * SA + k4 * 4) * 2) = hp;
        }
    };
    auto issue_b = [&](uint32_t stn, int k0) {
        #pragma unroll
        for (int l = 0; l < 6; l++) {
            int idx = l * 256 + tid;           // 0..1535
            int n = idx >> 3, u = idx & 7;
            uint32_t so = (uint32_t)(n * SA) * 2 + u * 16;
            CP_ASYNC16(stn + OFF_BH + so, g_wh + (size_t)n * CDIM + k0 + u * 8);
        }
        CP_COMMIT();
    };

    // ---- prologue ----
    load_x(0);
    issue_b(smb, 0);
    store_x(sm);
    CP_WAIT0();
    __syncthreads();

    for (int c = 0; c < NCH; c++) {
        const int s = c & 1;
        const uint32_t st = smb + s * STAGE;
        const bool more = (c + 1 < NCH);

        if (more) {
            load_x((c + 1) * BK);
            issue_b(smb + (s ^ 1) * STAGE, (c + 1) * BK);
        }

        #pragma unroll
        for (int ks = 0; ks < 4; ks++) {
            const int k0h = ks * 16;
            uint32_t ah[2][4], bf[6][4];
            #pragma unroll
            for (int mt = 0; mt < 2; mt++) {
                uint32_t ao = (uint32_t)((wm * 32 + mt * 16 + a_row) * SA + k0h + a_col) * 2;
                ldm_x4(ah[mt], st + OFF_A + ao);
            }
            #pragma unroll
            for (int g = 0; g < 6; g++) {
                uint32_t bo = (uint32_t)((wn * 96 + g * 16 + b_rowo) * SA + k0h + b_col) * 2;
                ldm_x4(bf[g], st + OFF_BH + bo);
            }
            #pragma unroll
            for (int mt = 0; mt < 2; mt++)
                #pragma unroll
                for (int g = 0; g < 6; g++) {
                    mma_f16(acc[mt][2 * g],     ah[mt], &bf[g][0]);
                    mma_f16(acc[mt][2 * g + 1], ah[mt], &bf[g][2]);
                }
        }

        if (more) {
            store_x(sm + (s ^ 1) * STAGE);
            CP_WAIT0();
            __syncthreads();
        }
    }

    // ---- epilogue ----
    const int grp = lane >> 2, tig = lane & 3;
    #pragma unroll
    for (int mt = 0; mt < 2; mt++) {
        const int row = m0 + wm * 32 + mt * 16 + grp;
        #pragma unroll
        for (int nt = 0; nt < 12; nt++) {
            const int col = wn * 96 + nt * 8 + tig * 2;
            *reinterpret_cast<float2*>(g_qkv + (size_t)row * QKVW + col) =
                make_float2(acc[mt][nt][0], acc[mt][nt][1]);
            *reinterpret_cast<float2*>(g_qkv + (size_t)(row + 8) * QKVW + col) =
                make_float2(acc[mt][nt][2], acc[mt][nt][3]);
        }
    }
}

// ---------------------------------------------------------------------------
// Attention: 128 queries/block, 2 lanes per query (dim halves), k/v in smem.
// ---------------------------------------------------------------------------
#define AT_ROWS 144
#define AT_STRIDE 66
#define ATT_SMEM (2 * AT_ROWS * AT_STRIDE * 4)   // 76032

__global__ __launch_bounds__(256)
void attn2(float* __restrict__ out) {
    extern __shared__ float smf[];
    float* const ks = smf;
    float* const vs = smf + AT_ROWS * AT_STRIDE;

    const int tid = threadIdx.x;
    const int b  = blockIdx.x >> 6;
    const int i0 = (blockIdx.x & 63) * 128;

    #pragma unroll
    for (int l = 0; l < 9; l++) {
        int lin = l * 256 + tid;           // 0..2303
        int idx = lin >> 4, c4 = lin & 15;
        int j = i0 - 16 + idx;
        float4 kv = make_float4(0.f, 0.f, 0.f, 0.f);
        float4 vv = make_float4(0.f, 0.f, 0.f, 0.f);
        if (j >= 0) {
            const float* src = g_qkv + (size_t)(b * SEQ + j) * QKVW;
            kv = *reinterpret_cast<const float4*>(src + HDIM + c4 * 4);
            vv = *reinterpret_cast<const float4*>(src + 2 * HDIM + c4 * 4);
        }
        int d = c4 * 4;
        int w = idx * AT_STRIDE + (d < 32 ? d : 33 + (d - 32));
        ks[w + 0] = kv.x; ks[w + 1] = kv.y; ks[w + 2] = kv.z; ks[w + 3] = kv.w;
        vs[w + 0] = vv.x; vs[w + 1] = vv.y; vs[w + 2] = vv.z; vs[w + 3] = vv.w;
    }

    const int lane = tid & 31;
    const int wrp = tid >> 5;
    const int qi = wrp * 16 + (lane & 15);   // 0..127
    const int h = lane >> 4;
    const int d0 = h * 32;
    const int i = i0 + qi;
    const size_t grow = (size_t)(b * SEQ + i);

    float q[32];
    {
        const float* qp = g_qkv + grow * QKVW + d0;
        #pragma unroll
        for (int cc = 0; cc < 32; cc += 4) {
            float4 t = *reinterpret_cast<const float4*>(qp + cc);
            q[cc] = t.x; q[cc + 1] = t.y; q[cc + 2] = t.z; q[cc + 3] = t.w;
        }
    }
    __syncthreads();

    float sc[17];
    float mx = -1e30f;
    #pragma unroll
    for (int t = 0; t < 17; t++) {
        const float* kr = ks + (qi + t) * AT_STRIDE + h * 33;
        float p0 = 0.f, p1 = 0.f, p2 = 0.f, p3 = 0.f;
        #pragma unroll
        for (int cc = 0; cc < 32; cc += 4) {
            p0 = fmaf(q[cc + 0], kr[cc + 0], p0);
            p1 = fmaf(q[cc + 1], kr[cc + 1], p1);
            p2 = fmaf(q[cc + 2], kr[cc + 2], p2);
            p3 = fmaf(q[cc + 3], kr[cc + 3], p3);
        }
        float p = (p0 + p1) + (p2 + p3);
        p += __shfl_xor_sync(0xffffffffu, p, 16);
        float d = (i - 16 + t >= 0) ? p * 0.125f : -1e30f;
        sc[t] = d;
        mx = fmaxf(mx, d);
    }

    float den = 0.f;
    #pragma unroll
    for (int t = 0; t < 17; t++) { sc[t] = __expf(sc[t] - mx); den += sc[t]; }
    const float inv = 1.0f / den;

    float* op = out + grow * HDIM + d0;
    #pragma unroll
    for (int cb = 0; cb < 32; cb += 4) {
        float a0 = 0.f, a1 = 0.f, a2 = 0.f, a3 = 0.f;
        #pragma unroll
        for (int t = 0; t < 17; t++) {
            const float* vr = vs + (qi + t) * AT_STRIDE + h * 33 + cb;
            a0 = fmaf(sc[t], vr[0], a0);
            a1 = fmaf(sc[t], vr[1], a1);
            a2 = fmaf(sc[t], vr[2], a2);
            a3 = fmaf(sc[t], vr[3], a3);
        }
        *reinterpret_cast<float4*>(op + cb) =
            make_float4(a0 * inv, a1 * inv, a2 * inv, a3 * inv);
    }
}

// ---------------------------------------------------------------------------
extern "C" void kernel_launch(void* const* d_in, const int* in_sizes, int n_in,
                              void* d_out, int out_size)
{
    const float* x  = (const float*)d_in[0];
    const float* Wq = (const float*)d_in[1];
    const float* Wk = (const float*)d_in[2];
    const float* Wv = (const float*)d_in[3];
    float* out = (float*)d_out;

    cudaFuncSetAttribute(qkv_gemm_mma, cudaFuncAttributeMaxDynamicSharedMemorySize, GEMM_SMEM);
    cudaFuncSetAttribute(attn2,        cudaFuncAttributeMaxDynamicSharedMemorySize, ATT_SMEM);

    conv_w<<<192, 256>>>(Wq, Wk, Wv);
    qkv_gemm_mma<<<NROWS / BM, 256, GEMM_SMEM>>>(x);
    attn2<<<128, 256, ATT_SMEM>>>(out);
}

// round 8
// speedup vs baseline: 5.1608x; 1.0577x over previous
#include <cuda_runtime.h>
#include <cuda_fp16.h>
#include <cstdint>

#define BATCH 2
#define SEQ   8192
#define CDIM  1024
#define HDIM  64
#define NROWS (BATCH * SEQ)   // 16384
#define QKVW  (3 * HDIM)      // 192

// ---- device scratch (no allocations) --------------------------------------
__device__ __half g_wh[QKVW * CDIM];             // W^T fp16  [192][1024]

// ---- helpers ----------------------------------------------------------------
__device__ __forceinline__ uint32_t smem_u32(const void* p) {
    uint32_t a;
    asm("{ .reg .u64 t; cvta.to.shared.u64 t, %1; cvt.u32.u64 %0, t; }"
        : "=r"(a) : "l"(p));
    return a;
}
__device__ __forceinline__ void ldm_x4(uint32_t* r, uint32_t addr) {
    asm volatile("ldmatrix.sync.aligned.m8n8.x4.shared.b16 {%0,%1,%2,%3}, [%4];"
        : "=r"(r[0]), "=r"(r[1]), "=r"(r[2]), "=r"(r[3]) : "r"(addr));
}
__device__ __forceinline__ void mma_f16(float* c, const uint32_t* a, const uint32_t* b) {
    asm volatile("mma.sync.aligned.m16n8k16.row.col.f32.f16.f16.f32 "
        "{%0,%1,%2,%3}, {%4,%5,%6,%7}, {%8,%9}, {%0,%1,%2,%3};"
        : "+f"(c[0]), "+f"(c[1]), "+f"(c[2]), "+f"(c[3])
        : "r"(a[0]), "r"(a[1]), "r"(a[2]), "r"(a[3]), "r"(b[0]), "r"(b[1]));
}
#define CP_ASYNC16(sm, gm) \
    asm volatile("cp.async.cg.shared.global [%0], [%1], 16;" :: "r"(sm), "l"(gm) : "memory")
#define CP_COMMIT() asm volatile("cp.async.commit_group;" ::: "memory")
#define CP_WAIT0()  asm volatile("cp.async.wait_group 0;" ::: "memory")

__device__ __forceinline__ uint32_t pack_h2(float a, float b) {
    __half2 t = __floats2half2_rn(a, b);
    return *reinterpret_cast<uint32_t*>(&t);
}

// ---------------------------------------------------------------------------
// Pre-pass: W fp32 [1024][64] x3  ->  W^T fp16 [192][1024]
// ---------------------------------------------------------------------------
__global__ __launch_bounds__(256)
void conv_w(const float* __restrict__ Wq,
            const float* __restrict__ Wk,
            const float* __restrict__ Wv) {
    __shared__ float ts[16][65];
    const int mat = blockIdx.x >> 6;          // 0..2
    const int k0  = (blockIdx.x & 63) * 16;   // k tile
    const float* W = (mat == 0) ? Wq : ((mat == 1) ? Wk : Wv);
    const int tid = threadIdx.x;

    const int ln = tid & 63, lk = tid >> 6;
    #pragma unroll
    for (int i = 0; i < 4; i++)
        ts[lk + i * 4][ln] = W[(size_t)(k0 + lk + i * 4) * 64 + ln];
    __syncthreads();

    const int n = tid >> 2, kq = (tid & 3) * 4;
    __half* hd = g_wh + (size_t)(mat * 64 + n) * CDIM + k0 + kq;
    __half2 a = __floats2half2_rn(ts[kq + 0][n], ts[kq + 1][n]);
    __half2 b = __floats2half2_rn(ts[kq + 2][n], ts[kq + 3][n]);
    *reinterpret_cast<__half2*>(hd)     = a;
    *reinterpret_cast<__half2*>(hd + 2) = b;
}

// ---------------------------------------------------------------------------
// Fused QKV GEMM + windowed attention.
// A tile: 144 rows = [m0-16, m0+128) clamped. N=192 (q|k|v). BK=64.
// 12 warps: 3 m-warps (48 rows) x 4 n-warps (48 cols). Warp tile 48x48.
// After GEMM: fragments scattered to padded smem (q/k/v), attention in-CTA.
// ---------------------------------------------------------------------------
#define MT   144
#define BK   64
#define NCH  (CDIM / BK)      // 16 chunks
#define SA   72               // A/B smem row stride in halfs
#define OFF_A  0
#define OFF_B  (MT * SA * 2)                       // 20736
#define STAGE  (OFF_B + QKVW * SA * 2)             // 48384
// attention overlay (floats): qs[128*66] | ks[144*66] | vs[144*66]
#define ATT_FLOATS ((128 + 144 + 144) * 66)        // 27456
#define FUSED_SMEM (ATT_FLOATS * 4 > 2 * STAGE ? ATT_FLOATS * 4 : 2 * STAGE)  // 109824

__global__ __launch_bounds__(384, 1)
void qkv_attn(const float* __restrict__ x, float* __restrict__ out) {
    extern __shared__ char sm[];
    const uint32_t smb = smem_u32(sm);
    float* const sp = reinterpret_cast<float*>(sm);
    float* const qs = sp;                 // [128][66]
    float* const ks = sp + 128 * 66;      // [144][66]
    float* const vs = ks + 144 * 66;      // [144][66]

    const int tid  = threadIdx.x;
    const int wid  = tid >> 5;
    const int lane = tid & 31;
    const int wm   = wid >> 2;       // 0..2
    const int wn   = wid & 3;        // 0..3
    const int m0   = blockIdx.x * 128;

    float acc[3][6][4];
    #pragma unroll
    for (int mt = 0; mt < 3; mt++)
        #pragma unroll
        for (int nt = 0; nt < 6; nt++)
            #pragma unroll
            for (int q = 0; q < 4; q++) acc[mt][nt][q] = 0.f;

    const int a_row  = (lane & 15);
    const int a_col  = (lane >> 4) * 8;
    const int b_rowo = ((lane >> 4) << 3) + (lane & 7);
    const int b_col  = ((lane >> 3) & 1) * 8;

    // x loader: 144 rows x 16 float4 = 2304 -> 6 per thread
    float4 xf[6];
    auto load_x = [&](int k0) {
        #pragma unroll
        for (int l = 0; l < 6; l++) {
            int idx = l * 384 + tid;
            int row = idx >> 4, c4 = idx & 15;
            int gr = m0 - 16 + row;
            gr = gr < 0 ? 0 : gr;
            xf[l] = *reinterpret_cast<const float4*>(
                x + (size_t)gr * CDIM + k0 + c4 * 4);
        }
    };
    auto store_x = [&](char* stp) {
        #pragma unroll
        for (int l = 0; l < 6; l++) {
            int idx = l * 384 + tid;
            int row = idx >> 4, c4 = idx & 15;
            uint2 hp = make_uint2(pack_h2(xf[l].x, xf[l].y), pack_h2(xf[l].z, xf[l].w));
            *reinterpret_cast<uint2*>(stp + OFF_A + (uint32_t)(row * SA + c4 * 4) * 2) = hp;
        }
    };
    // B loader: 192 rows x 8 16B-units = 1536 -> 4 per thread
    auto issue_b = [&](uint32_t stn, int k0) {
        #pragma unroll
        for (int l = 0; l < 4; l++) {
            int idx = l * 384 + tid;
            int n = idx >> 3, u = idx & 7;
            uint32_t so = (uint32_t)(n * SA) * 2 + u * 16;
            CP_ASYNC16(stn + OFF_B + so, g_wh + (size_t)n * CDIM + k0 + u * 8);
        }
        CP_COMMIT();
    };

    // ---- prologue ----
    load_x(0);
    issue_b(smb, 0);
    store_x(sm);
    CP_WAIT0();
    __syncthreads();

    for (int c = 0; c < NCH; c++) {
        const int s = c & 1;
        const uint32_t st = smb + s * STAGE;
        const bool more = (c + 1 < NCH);

        if (more) {
            load_x((c + 1) * BK);
            issue_b(smb + (s ^ 1) * STAGE, (c + 1) * BK);
        }

        #pragma unroll
        for (int ksp = 0; ksp < 4; ksp++) {
            const int k0h = ksp * 16;
            uint32_t ah[3][4], bf[3][4];
            #pragma unroll
            for (int mt = 0; mt < 3; mt++) {
                uint32_t ao = (uint32_t)((wm * 48 + mt * 16 + a_row) * SA + k0h + a_col) * 2;
                ldm_x4(ah[mt], st + OFF_A + ao);
            }
            #pragma unroll
            for (int g = 0; g < 3; g++) {
                uint32_t bo = (uint32_t)((wn * 48 + g * 16 + b_rowo) * SA + k0h + b_col) * 2;
                ldm_x4(bf[g], st + OFF_B + bo);
            }
            #pragma unroll
            for (int mt = 0; mt < 3; mt++)
                #pragma unroll
                for (int g = 0; g < 3; g++) {
                    mma_f16(acc[mt][2 * g],     ah[mt], &bf[g][0]);
                    mma_f16(acc[mt][2 * g + 1], ah[mt], &bf[g][2]);
                }
        }

        if (more) {
            store_x(sm + (s ^ 1) * STAGE);
            CP_WAIT0();
            __syncthreads();
        }
    }

    // ---- scatter fragments into attention smem layout (scalar stores:
    //      padded offsets can be odd words -> no 8B vector stores here) ----
    __syncthreads();   // stages dead for everyone before overlay writes
    {
        const int grp = lane >> 2, tig = lane & 3;
        #pragma unroll
        for (int mt = 0; mt < 3; mt++) {
            #pragma unroll
            for (int nt = 0; nt < 6; nt++) {
                const int col = wn * 48 + nt * 8 + tig * 2;
                const int cm = col & 63;
                const int ho = (cm < 32) ? cm : cm + 1;    // padded half offset
                #pragma unroll
                for (int half = 0; half < 2; half++) {
                    const int row = wm * 48 + mt * 16 + grp + half * 8;
                    float v0 = acc[mt][nt][half * 2];
                    float v1 = acc[mt][nt][half * 2 + 1];
                    if (col < 64) {
                        if (row >= 16) {
                            float* p = qs + (row - 16) * 66 + ho;
                            p[0] = v0; p[1] = v1;
                        }
                    } else if (col < 128) {
                        float* p = ks + row * 66 + ho;
                        p[0] = v0; p[1] = v1;
                    } else {
                        float* p = vs + row * 66 + ho;
                        p[0] = v0; p[1] = v1;
                    }
                }
            }
        }
    }
    __syncthreads();

    // ---- attention: warps 0..7, 16 queries x 2 dim-halves per warp ----
    if (wid < 8) {
        const int qi = wid * 16 + (lane & 15);     // 0..127
        const int h  = lane >> 4;
        const int d0 = h * 32;
        const int i  = (m0 + qi) & (SEQ - 1);      // batch-local position

        float q[32];
        {
            const float* qp = qs + qi * 66 + h * 33;
            #pragma unroll
            for (int cc = 0; cc < 32; cc++) q[cc] = qp[cc];
        }

        float sc[17];
        float mx = -1e30f;
        #pragma unroll
        for (int t = 0; t < 17; t++) {
            const float* kr = ks + (qi + t) * 66 + h * 33;
            float p0 = 0.f, p1 = 0.f, p2 = 0.f, p3 = 0.f;
            #pragma unroll
            for (int cc = 0; cc < 32; cc += 4) {
                p0 = fmaf(q[cc + 0], kr[cc + 0], p0);
                p1 = fmaf(q[cc + 1], kr[cc + 1], p1);
                p2 = fmaf(q[cc + 2], kr[cc + 2], p2);
                p3 = fmaf(q[cc + 3], kr[cc + 3], p3);
            }
            float p = (p0 + p1) + (p2 + p3);
            p += __shfl_xor_sync(0xffffffffu, p, 16);
            float d = (i - 16 + t >= 0) ? p * 0.125f : -1e30f;
            sc[t] = d;
            mx = fmaxf(mx, d);
        }

        float den = 0.f;
        #pragma unroll
        for (int t = 0; t < 17; t++) { sc[t] = __expf(sc[t] - mx); den += sc[t]; }
        const float inv = 1.0f / den;

        float* op = out + (size_t)(m0 + qi) * HDIM + d0;
        #pragma unroll
        for (int cb = 0; cb < 32; cb += 4) {
            float a0 = 0.f, a1 = 0.f, a2 = 0.f, a3 = 0.f;
            #pragma unroll
            for (int t = 0; t < 17; t++) {
                const float* vr = vs + (qi + t) * 66 + h * 33 + cb;
                a0 = fmaf(sc[t], vr[0], a0);
                a1 = fmaf(sc[t], vr[1], a1);
                a2 = fmaf(sc[t], vr[2], a2);
                a3 = fmaf(sc[t], vr[3], a3);
            }
            *reinterpret_cast<float4*>(op + cb) =
                make_float4(a0 * inv, a1 * inv, a2 * inv, a3 * inv);
        }
    }
}

// ---------------------------------------------------------------------------
extern "C" void kernel_launch(void* const* d_in, const int* in_sizes, int n_in,
                              void* d_out, int out_size)
{
    const float* x  = (const float*)d_in[0];
    const float* Wq = (const float*)d_in[1];
    const float* Wk = (const float*)d_in[2];
    const float* Wv = (const float*)d_in[3];
    float* out = (float*)d_out;

    cudaFuncSetAttribute(qkv_attn, cudaFuncAttributeMaxDynamicSharedMemorySize, FUSED_SMEM);

    conv_w<<<192, 256>>>(Wq, Wk, Wv);
    qkv_attn<<<NROWS / 128, 384, FUSED_SMEM>>>(x, out);
}

// round 9
// speedup vs baseline: 5.4392x; 1.0539x over previous
#include <cuda_runtime.h>
#include <cuda_fp16.h>
#include <cstdint>

#define BATCH 2
#define SEQ   8192
#define CDIM  1024
#define HDIM  64
#define NROWS (BATCH * SEQ)   // 16384
#define QKVW  (3 * HDIM)      // 192

// ---- device scratch (no allocations) --------------------------------------
__device__ __half g_wh[QKVW * CDIM];             // W^T fp16  [192][1024]

// ---- helpers ----------------------------------------------------------------
__device__ __forceinline__ uint32_t smem_u32(const void* p) {
    uint32_t a;
    asm("{ .reg .u64 t; cvta.to.shared.u64 t, %1; cvt.u32.u64 %0, t; }"
        : "=r"(a) : "l"(p));
    return a;
}
__device__ __forceinline__ void ldm_x4(uint32_t* r, uint32_t addr) {
    asm volatile("ldmatrix.sync.aligned.m8n8.x4.shared.b16 {%0,%1,%2,%3}, [%4];"
        : "=r"(r[0]), "=r"(r[1]), "=r"(r[2]), "=r"(r[3]) : "r"(addr));
}
__device__ __forceinline__ void mma_f16(float* c, const uint32_t* a, const uint32_t* b) {
    asm volatile("mma.sync.aligned.m16n8k16.row.col.f32.f16.f16.f32 "
        "{%0,%1,%2,%3}, {%4,%5,%6,%7}, {%8,%9}, {%0,%1,%2,%3};"
        : "+f"(c[0]), "+f"(c[1]), "+f"(c[2]), "+f"(c[3])
        : "r"(a[0]), "r"(a[1]), "r"(a[2]), "r"(a[3]), "r"(b[0]), "r"(b[1]));
}
#define CP_ASYNC16(sm, gm) \
    asm volatile("cp.async.cg.shared.global [%0], [%1], 16;" :: "r"(sm), "l"(gm) : "memory")
#define CP_COMMIT() asm volatile("cp.async.commit_group;" ::: "memory")
#define CP_WAIT0()  asm volatile("cp.async.wait_group 0;" ::: "memory")

__device__ __forceinline__ uint32_t pack_h2(float a, float b) {
    __half2 t = __floats2half2_rn(a, b);
    return *reinterpret_cast<uint32_t*>(&t);
}

// ---------------------------------------------------------------------------
// Pre-pass: W fp32 [1024][64] x3  ->  W^T fp16 [192][1024]
// ---------------------------------------------------------------------------
__global__ __launch_bounds__(256)
void conv_w(const float* __restrict__ Wq,
            const float* __restrict__ Wk,
            const float* __restrict__ Wv) {
    __shared__ float ts[16][65];
    const int mat = blockIdx.x >> 6;          // 0..2
    const int k0  = (blockIdx.x & 63) * 16;   // k tile
    const float* W = (mat == 0) ? Wq : ((mat == 1) ? Wk : Wv);
    const int tid = threadIdx.x;

    const int ln = tid & 63, lk = tid >> 6;
    #pragma unroll
    for (int i = 0; i < 4; i++)
        ts[lk + i * 4][ln] = W[(size_t)(k0 + lk + i * 4) * 64 + ln];
    __syncthreads();

    const int n = tid >> 2, kq = (tid & 3) * 4;
    __half* hd = g_wh + (size_t)(mat * 64 + n) * CDIM + k0 + kq;
    __half2 a = __floats2half2_rn(ts[kq + 0][n], ts[kq + 1][n]);
    __half2 b = __floats2half2_rn(ts[kq + 2][n], ts[kq + 3][n]);
    *reinterpret_cast<__half2*>(hd)     = a;
    *reinterpret_cast<__half2*>(hd + 2) = b;
}

// ---------------------------------------------------------------------------
// Fused QKV GEMM + windowed attention.
// 112 queries per CTA; A tile = 128 rows [m0-16, m0+112) clamped. N=192. BK=64.
// grid = 147 (one wave on 148 SMs). 12 warps: 2m x 6n, warp tile 64x32.
// ---------------------------------------------------------------------------
#define MTQ  112              // queries per CTA
#define MA   128              // A tile rows (16 halo + 112)
#define BK   64
#define NCH  (CDIM / BK)      // 16 chunks
#define SA   72               // A/B smem row stride in halfs
#define OFF_A  0
#define OFF_B  (MA * SA * 2)                       // 18432
#define STAGE  (OFF_B + QKVW * SA * 2)             // 46080
// attention overlay (floats): qs[112*66] | ks[128*66] | vs[128*66]
#define ATT_FLOATS ((MTQ + MA + MA) * 66)          // 24288
#define FUSED_SMEM (ATT_FLOATS * 4 > 2 * STAGE ? ATT_FLOATS * 4 : 2 * STAGE)  // 97152

__global__ __launch_bounds__(384, 1)
void qkv_attn(const float* __restrict__ x, float* __restrict__ out) {
    extern __shared__ char sm[];
    const uint32_t smb = smem_u32(sm);
    float* const sp = reinterpret_cast<float*>(sm);
    float* const qs = sp;                 // [112][66]
    float* const ks = sp + MTQ * 66;      // [128][66]
    float* const vs = ks + MA * 66;       // [128][66]

    const int tid  = threadIdx.x;
    const int wid  = tid >> 5;
    const int lane = tid & 31;
    const int wm   = wid >> 2 >= 1 ? (wid >= 6 ? 1 : 0) : 0;  // placeholder, fixed below
    const int wmm  = wid / 6;        // 0..1  (m-warp)
    const int wn   = wid % 6;        // 0..5  (n-warp)
    const int m0   = blockIdx.x * MTQ;
    (void)wm;

    float acc[4][4][4];
    #pragma unroll
    for (int mt = 0; mt < 4; mt++)
        #pragma unroll
        for (int nt = 0; nt < 4; nt++)
            #pragma unroll
            for (int q = 0; q < 4; q++) acc[mt][nt][q] = 0.f;

    const int a_row  = (lane & 15);
    const int a_col  = (lane >> 4) * 8;
    const int b_rowo = ((lane >> 4) << 3) + (lane & 7);
    const int b_col  = ((lane >> 3) & 1) * 8;

    // x loader: 128 rows x 16 float4 = 2048 -> <=6 per thread (l=5 partial)
    float4 xf[6];
    auto load_x = [&](int k0) {
        #pragma unroll
        for (int l = 0; l < 6; l++) {
            int idx = l * 384 + tid;
            if (idx < MA * 16) {
                int row = idx >> 4, c4 = idx & 15;
                int gr = m0 - 16 + row;
                gr = gr < 0 ? 0 : (gr >= NROWS ? NROWS - 1 : gr);
                xf[l] = *reinterpret_cast<const float4*>(
                    x + (size_t)gr * CDIM + k0 + c4 * 4);
            }
        }
    };
    auto store_x = [&](char* stp) {
        #pragma unroll
        for (int l = 0; l < 6; l++) {
            int idx = l * 384 + tid;
            if (idx < MA * 16) {
                int row = idx >> 4, c4 = idx & 15;
                uint2 hp = make_uint2(pack_h2(xf[l].x, xf[l].y), pack_h2(xf[l].z, xf[l].w));
                *reinterpret_cast<uint2*>(stp + OFF_A + (uint32_t)(row * SA + c4 * 4) * 2) = hp;
            }
        }
    };
    // B loader: 192 rows x 8 16B-units = 1536 -> 4 per thread
    auto issue_b = [&](uint32_t stn, int k0) {
        #pragma unroll
        for (int l = 0; l < 4; l++) {
            int idx = l * 384 + tid;
            int n = idx >> 3, u = idx & 7;
            uint32_t so = (uint32_t)(n * SA) * 2 + u * 16;
            CP_ASYNC16(stn + OFF_B + so, g_wh + (size_t)n * CDIM + k0 + u * 8);
        }
        CP_COMMIT();
    };

    // ---- prologue ----
    load_x(0);
    issue_b(smb, 0);
    store_x(sm);
    CP_WAIT0();
    __syncthreads();

    for (int c = 0; c < NCH; c++) {
        const int s = c & 1;
        const uint32_t st = smb + s * STAGE;
        const bool more = (c + 1 < NCH);

        if (more) {
            load_x((c + 1) * BK);
            issue_b(smb + (s ^ 1) * STAGE, (c + 1) * BK);
        }

        #pragma unroll
        for (int ksp = 0; ksp < 4; ksp++) {
            const int k0h = ksp * 16;
            uint32_t ah[4][4], bf[2][4];
            #pragma unroll
            for (int mt = 0; mt < 4; mt++) {
                uint32_t ao = (uint32_t)((wmm * 64 + mt * 16 + a_row) * SA + k0h + a_col) * 2;
                ldm_x4(ah[mt], st + OFF_A + ao);
            }
            #pragma unroll
            for (int g = 0; g < 2; g++) {
                uint32_t bo = (uint32_t)((wn * 32 + g * 16 + b_rowo) * SA + k0h + b_col) * 2;
                ldm_x4(bf[g], st + OFF_B + bo);
            }
            #pragma unroll
            for (int mt = 0; mt < 4; mt++)
                #pragma unroll
                for (int g = 0; g < 2; g++) {
                    mma_f16(acc[mt][2 * g],     ah[mt], &bf[g][0]);
                    mma_f16(acc[mt][2 * g + 1], ah[mt], &bf[g][2]);
                }
        }

        if (more) {
            store_x(sm + (s ^ 1) * STAGE);
            CP_WAIT0();
            __syncthreads();
        }
    }

    // ---- scatter fragments into attention smem layout (scalar stores) ----
    __syncthreads();
    {
        const int grp = lane >> 2, tig = lane & 3;
        #pragma unroll
        for (int mt = 0; mt < 4; mt++) {
            #pragma unroll
            for (int nt = 0; nt < 4; nt++) {
                const int col = wn * 32 + nt * 8 + tig * 2;
                const int cm = col & 63;
                const int ho = (cm < 32) ? cm : cm + 1;    // padded half offset
                #pragma unroll
                for (int half = 0; half < 2; half++) {
                    const int row = wmm * 64 + mt * 16 + grp + half * 8;
                    float v0 = acc[mt][nt][half * 2];
                    float v1 = acc[mt][nt][half * 2 + 1];
                    if (col < 64) {
                        if (row >= 16) {
                            float* p = qs + (row - 16) * 66 + ho;
                            p[0] = v0; p[1] = v1;
                        }
                    } else if (col < 128) {
                        float* p = ks + row * 66 + ho;
                        p[0] = v0; p[1] = v1;
                    } else {
                        float* p = vs + row * 66 + ho;
                        p[0] = v0; p[1] = v1;
                    }
                }
            }
        }
    }
    __syncthreads();

    // ---- attention: warps 0..6, 16 queries x 2 dim-halves per warp ----
    if (wid < 7) {
        const int qi = wid * 16 + (lane & 15);     // 0..111
        const int h  = lane >> 4;
        const int d0 = h * 32;
        const int gq = m0 + qi;                    // global query row
        const int i  = gq & (SEQ - 1);             // batch-local position

        float q[32];
        {
            const float* qp = qs + qi * 66 + h * 33;
            #pragma unroll
            for (int cc = 0; cc < 32; cc++) q[cc] = qp[cc];
        }

        float sc[17];
        float mx = -1e30f;
        #pragma unroll
        for (int t = 0; t < 17; t++) {
            const float* kr = ks + (qi + t) * 66 + h * 33;
            float p0 = 0.f, p1 = 0.f, p2 = 0.f, p3 = 0.f;
            #pragma unroll
            for (int cc = 0; cc < 32; cc += 4) {
                p0 = fmaf(q[cc + 0], kr[cc + 0], p0);
                p1 = fmaf(q[cc + 1], kr[cc + 1], p1);
                p2 = fmaf(q[cc + 2], kr[cc + 2], p2);
                p3 = fmaf(q[cc + 3], kr[cc + 3], p3);
            }
            float p = (p0 + p1) + (p2 + p3);
            p += __shfl_xor_sync(0xffffffffu, p, 16);
            float d = (i - 16 + t >= 0) ? p * 0.125f : -1e30f;
            sc[t] = d;
            mx = fmaxf(mx, d);
        }

        float den = 0.f;
        #pragma unroll
        for (int t = 0; t < 17; t++) { sc[t] = __expf(sc[t] - mx); den += sc[t]; }
        const float inv = 1.0f / den;

        if (gq < NROWS) {
            float* op = out + (size_t)gq * HDIM + d0;
            #pragma unroll
            for (int cb = 0; cb < 32; cb += 4) {
                float a0 = 0.f, a1 = 0.f, a2 = 0.f, a3 = 0.f;
                #pragma unroll
                for (int t = 0; t < 17; t++) {
                    const float* vr = vs + (qi + t) * 66 + h * 33 + cb;
                    a0 = fmaf(sc[t], vr[0], a0);
                    a1 = fmaf(sc[t], vr[1], a1);
                    a2 = fmaf(sc[t], vr[2], a2);
                    a3 = fmaf(sc[t], vr[3], a3);
                }
                *reinterpret_cast<float4*>(op + cb) =
                    make_float4(a0 * inv, a1 * inv, a2 * inv, a3 * inv);
            }
        }
    }
}

// ---------------------------------------------------------------------------
extern "C" void kernel_launch(void* const* d_in, const int* in_sizes, int n_in,
                              void* d_out, int out_size)
{
    const float* x  = (const float*)d_in[0];
    const float* Wq = (const float*)d_in[1];
    const float* Wk = (const float*)d_in[2];
    const float* Wv = (const float*)d_in[3];
    float* out = (float*)d_out;

    cudaFuncSetAttribute(qkv_attn, cudaFuncAttributeMaxDynamicSharedMemorySize, FUSED_SMEM);

    const int grid = (NROWS + MTQ - 1) / MTQ;   // 147
    conv_w<<<192, 256>>>(Wq, Wk, Wv);
    qkv_attn<<<grid, 384, FUSED_SMEM>>>(x, out);
}